// round 7
// baseline (speedup 1.0000x reference)
#include <cuda_runtime.h>
#include <cuda_bf16.h>
#include <cstdint>

#define NN 50000
#define EE 400000
#define HH 128
#define DD 15
#define GG 256

// ---------------- device scratch (no allocations allowed) ----------------
__device__ __align__(16) float g_bufA[(size_t)EE * HH];
__device__ __align__(16) float g_bufB[(size_t)EE * HH];
__device__ __align__(16) float g_amsg[(size_t)NN * HH];
// conv weights as 2 bf16 limbs, [d][n][k] row-major (mma B operand layout)
__device__ __align__(16) __nv_bfloat16 g_WbH[DD * HH * HH];
__device__ __align__(16) __nv_bfloat16 g_WbL[DD * HH * HH];
// edge-init weights (tf32 2-limb legacy path)
__device__ __align__(16) float g_EiHi[64 * HH];
__device__ __align__(16) float g_EiLo[64 * HH];
__device__ __align__(16) float g_alpha[DD * HH];
__device__ __align__(16) float g_beta[DD * HH];
__device__ int g_cnt[NN];
__device__ int g_rowptr[NN + 1];
__device__ int g_cursor[NN];
__device__ int g_csr[EE];

// ---------------- helpers ----------------
__device__ __forceinline__ void tf32_split(float v, float& hi, float& lo) {
    unsigned h;
    asm("cvt.rna.tf32.f32 %0, %1;" : "=r"(h) : "f"(v));
    float hf = __uint_as_float(h);
    float r = v - hf;
    unsigned l;
    asm("cvt.rna.tf32.f32 %0, %1;" : "=r"(l) : "f"(r));
    hi = hf;
    lo = __uint_as_float(l);
}

__device__ __forceinline__ void bf16_split2(float v, __nv_bfloat16& h, __nv_bfloat16& l) {
    h = __float2bfloat16(v);
    l = __float2bfloat16(v - __bfloat162float(h));
}

#define MMA_TF32(c, a, b)                                                    \
    asm volatile(                                                            \
        "mma.sync.aligned.m16n8k8.row.col.f32.tf32.tf32.f32 "                \
        "{%0,%1,%2,%3},{%4,%5,%6,%7},{%8,%9},{%0,%1,%2,%3};"                 \
        : "+f"((c)[0]), "+f"((c)[1]), "+f"((c)[2]), "+f"((c)[3])             \
        : "r"((a)[0]), "r"((a)[1]), "r"((a)[2]), "r"((a)[3]),                \
          "r"((b)[0]), "r"((b)[1]))

#define MMA_BF16(c, a, b)                                                    \
    asm volatile(                                                            \
        "mma.sync.aligned.m16n8k16.row.col.f32.bf16.bf16.f32 "               \
        "{%0,%1,%2,%3},{%4,%5,%6,%7},{%8,%9},{%0,%1,%2,%3};"                 \
        : "+f"((c)[0]), "+f"((c)[1]), "+f"((c)[2]), "+f"((c)[3])             \
        : "r"((a)[0]), "r"((a)[1]), "r"((a)[2]), "r"((a)[3]),                \
          "r"((b)[0]), "r"((b)[1]))

#define LDSM_X4(r0, r1, r2, r3, addr)                                        \
    asm volatile("ldmatrix.sync.aligned.m8n8.x4.shared.b16 {%0,%1,%2,%3}, [%4];" \
                 : "=r"(r0), "=r"(r1), "=r"(r2), "=r"(r3) : "r"(addr))

// ---------------- CSR build (by col) ----------------
__global__ void k_zero_cnt() {
    int i = blockIdx.x * blockDim.x + threadIdx.x;
    if (i < NN) g_cnt[i] = 0;
}

__global__ void k_count(const int* __restrict__ col) {
    int e = blockIdx.x * blockDim.x + threadIdx.x;
    if (e < EE) atomicAdd(&g_cnt[col[e]], 1);
}

__global__ void k_scan() {
    __shared__ int sh[1024];
    int t = threadIdx.x;
    const int C = (NN + 1023) / 1024;
    int base = t * C;
    int s = 0;
    for (int j = 0; j < C; j++) {
        int i = base + j;
        if (i < NN) s += g_cnt[i];
    }
    sh[t] = s;
    __syncthreads();
    for (int off = 1; off < 1024; off <<= 1) {
        int v = (t >= off) ? sh[t - off] : 0;
        __syncthreads();
        sh[t] += v;
        __syncthreads();
    }
    int run = sh[t] - s;
    for (int j = 0; j < C; j++) {
        int i = base + j;
        if (i < NN) {
            g_rowptr[i] = run;
            g_cursor[i] = run;
            run += g_cnt[i];
        }
    }
    if (t == 0) g_rowptr[NN] = EE;
}

__global__ void k_scatter(const int* __restrict__ col) {
    int e = blockIdx.x * blockDim.x + threadIdx.x;
    if (e < EE) {
        int pos = atomicAdd(&g_cursor[col[e]], 1);
        g_csr[pos] = e;
    }
}

__global__ void k_sortcsr() {
    int i = blockIdx.x * blockDim.x + threadIdx.x;
    if (i >= NN) return;
    int s = g_rowptr[i], e = g_rowptr[i + 1];
    for (int a = s + 1; a < e; a++) {
        int v = g_csr[a];
        int b = a - 1;
        while (b >= s && g_csr[b] > v) { g_csr[b + 1] = g_csr[b]; b--; }
        g_csr[b + 1] = v;
    }
}

// ---------------- parameter prep ----------------
__global__ void k_prep_w(const float* __restrict__ W) {
    int idx = blockIdx.x * blockDim.x + threadIdx.x;
    if (idx >= DD * HH * HH) return;
    float v = W[idx];
    __nv_bfloat16 h, l;
    bf16_split2(v, h, l);
    g_WbH[idx] = h;
    g_WbL[idx] = l;
}

__global__ void k_prep_wei(const float* __restrict__ W) {
    int idx = blockIdx.x * blockDim.x + threadIdx.x;
    if (idx >= 64 * HH) return;
    int k = idx >> 7, o = idx & 127;
    float v = (k < 61) ? W[o * 61 + k] : 0.f;
    float hi, lo;
    tf32_split(v, hi, lo);
    g_EiHi[idx] = hi;
    g_EiLo[idx] = lo;
}

__global__ void k_prep_bn(const float* __restrict__ b, const float* __restrict__ gm,
                          const float* __restrict__ bt, const float* __restrict__ rm,
                          const float* __restrict__ rv) {
    int idx = blockIdx.x * blockDim.x + threadIdx.x;
    if (idx >= DD * HH) return;
    float al = gm[idx] * rsqrtf(rv[idx] + 1e-5f);
    g_alpha[idx] = al;
    g_beta[idx] = al * (b[idx] - rm[idx]) + bt[idx];
}

// ---------------- a_msg / h_node: warp-per-node CSR gather ----------------
__global__ __launch_bounds__(256) void k_amsg(int flip) {
    const float* __restrict__ src = flip ? g_bufB : g_bufA;
    int w = (blockIdx.x * 256 + threadIdx.x) >> 5;
    int lane = threadIdx.x & 31;
    if (w >= NN) return;
    int s = g_rowptr[w], e = g_rowptr[w + 1];
    float4 acc = make_float4(0.f, 0.f, 0.f, 0.f);
    for (int j = s; j < e; j++) {
        int ed = g_csr[j];
        float4 v = reinterpret_cast<const float4*>(src)[(size_t)ed * 32 + lane];
        acc.x += v.x; acc.y += v.y; acc.z += v.z; acc.w += v.w;
    }
    reinterpret_cast<float4*>(g_amsg)[(size_t)w * 32 + lane] = acc;
}

// ---------------- fused DMPNN layer GEMM: bf16 2-limb, 3 passes, ldmatrix feed ----------------
// dst[e] = 2*relu(alpha * ((a_msg[row[e]] - src[e^1]) @ W^T) + beta)
#define PB 136  // bf16 pitch (272B): row stride shifts 4 banks -> ldmatrix conflict-free
#define PLANE (128 * PB)
#define SMEM_GEMM ((256) * 4 + 4 * PLANE * 2)

__global__ __launch_bounds__(256, 1) void k_gemm(int flip, int layer,
                                                 const int* __restrict__ row) {
    const float* __restrict__ src = flip ? g_bufB : g_bufA;
    float* __restrict__ dst = flip ? g_bufA : g_bufB;
    extern __shared__ __align__(16) char smg[];
    float* als = (float*)smg;
    float* bes = als + 128;
    __nv_bfloat16* AsH = (__nv_bfloat16*)(bes + 128);
    __nv_bfloat16* AsL = AsH + PLANE;
    __nv_bfloat16* BsH = AsL + PLANE;
    __nv_bfloat16* BsL = BsH + PLANE;

    int tid = threadIdx.x;
    int e0 = blockIdx.x * 128;

    if (tid < 128) {
        als[tid] = g_alpha[layer * HH + tid];
        bes[tid] = g_beta[layer * HH + tid];
    }

    // B planes: 128 rows x 16 float4 per plane
    {
        const float4* wh = (const float4*)(g_WbH + (size_t)layer * HH * HH);
        const float4* wl = (const float4*)(g_WbL + (size_t)layer * HH * HH);
        for (int i = tid; i < 2048; i += 256) {
            int n = i >> 4, c = i & 15;
            *reinterpret_cast<float4*>(&BsH[n * PB + c * 8]) = wh[i];
            *reinterpret_cast<float4*>(&BsL[n * PB + c * 8]) = wl[i];
        }
    }

    // A planes: msg = a_msg[row[e]] - src[e^1], split to bf16 hi/lo once
    for (int i = tid; i < 4096; i += 256) {
        int m = i >> 5, k4 = i & 31;
        int e = e0 + m;
        int r = __ldg(&row[e]);
        float4 am = reinterpret_cast<const float4*>(g_amsg)[(size_t)r * 32 + k4];
        float4 rv = reinterpret_cast<const float4*>(src)[((size_t)(e ^ 1)) * 32 + k4];
        float v0 = am.x - rv.x, v1 = am.y - rv.y, v2 = am.z - rv.z, v3 = am.w - rv.w;
        __nv_bfloat16 h0, h1, h2, h3, l0, l1, l2, l3;
        bf16_split2(v0, h0, l0);
        bf16_split2(v1, h1, l1);
        bf16_split2(v2, h2, l2);
        bf16_split2(v3, h3, l3);
        int base = m * PB + (k4 << 2);
        *reinterpret_cast<__nv_bfloat162*>(&AsH[base]) = __halves2bfloat162(h0, h1);
        *reinterpret_cast<__nv_bfloat162*>(&AsH[base + 2]) = __halves2bfloat162(h2, h3);
        *reinterpret_cast<__nv_bfloat162*>(&AsL[base]) = __halves2bfloat162(l0, l1);
        *reinterpret_cast<__nv_bfloat162*>(&AsL[base + 2]) = __halves2bfloat162(l2, l3);
    }
    __syncthreads();

    int lane = tid & 31, w = tid >> 5;
    int m0 = (w >> 2) * 64, n0 = (w & 3) * 32;
    int gid = lane >> 2, tg = lane & 3;

    // ldmatrix per-lane addresses (byte offsets in shared space)
    // A x4: m0..m3 = (rows0-7,k0-7),(rows8-15,k0-7),(rows0-7,k8-15),(rows8-15,k8-15)
    unsigned rowA = (lane & 7) + ((lane >> 3) & 1) * 8;
    unsigned colA = (lane >> 4) * 8;
    // B x4 (pair p covers nf=2p,2p+1): m0=(nf0,k0-7), m1=(nf0,k8-15), m2=(nf1,k0-7), m3=(nf1,k8-15)
    unsigned rowB = ((lane >> 4) & 1) * 8 + (lane & 7);
    unsigned colB = ((lane >> 3) & 1) * 8;

    unsigned aH0 = (unsigned)__cvta_generic_to_shared(&AsH[(m0 + rowA) * PB + colA]);
    unsigned aL0 = (unsigned)__cvta_generic_to_shared(&AsL[(m0 + rowA) * PB + colA]);
    unsigned bH0 = (unsigned)__cvta_generic_to_shared(&BsH[(n0 + rowB) * PB + colB]);
    unsigned bL0 = (unsigned)__cvta_generic_to_shared(&BsL[(n0 + rowB) * PB + colB]);

    float acc[4][4][4];
#pragma unroll
    for (int mf = 0; mf < 4; mf++)
#pragma unroll
        for (int nf = 0; nf < 4; nf++)
#pragma unroll
            for (int q = 0; q < 4; q++) acc[mf][nf][q] = 0.f;

#pragma unroll 1
    for (int ks = 0; ks < 8; ks++) {
        unsigned koff = ks * 32;  // 16 bf16 = 32 bytes
        unsigned ah[4][4], al[4][4];
#pragma unroll
        for (int mf = 0; mf < 4; mf++) {
            unsigned off = mf * (16 * PB * 2) + koff;
            LDSM_X4(ah[mf][0], ah[mf][1], ah[mf][2], ah[mf][3], aH0 + off);
            LDSM_X4(al[mf][0], al[mf][1], al[mf][2], al[mf][3], aL0 + off);
        }
        unsigned bh[4][2], bl[4][2];
#pragma unroll
        for (int p = 0; p < 2; p++) {
            unsigned off = p * (16 * PB * 2) + koff;
            LDSM_X4(bh[2 * p][0], bh[2 * p][1], bh[2 * p + 1][0], bh[2 * p + 1][1], bH0 + off);
            LDSM_X4(bl[2 * p][0], bl[2 * p][1], bl[2 * p + 1][0], bl[2 * p + 1][1], bL0 + off);
        }
#pragma unroll
        for (int mf = 0; mf < 4; mf++)
#pragma unroll
            for (int nf = 0; nf < 4; nf++) {
                MMA_BF16(acc[mf][nf], ah[mf], bh[nf]);
                MMA_BF16(acc[mf][nf], ah[mf], bl[nf]);
                MMA_BF16(acc[mf][nf], al[mf], bh[nf]);
            }
    }

    // epilogue: 2*relu(alpha*acc + beta)
#pragma unroll
    for (int nf = 0; nf < 4; nf++) {
        int c = n0 + nf * 8 + 2 * tg;
        float2 a2 = *reinterpret_cast<const float2*>(&als[c]);
        float2 b2 = *reinterpret_cast<const float2*>(&bes[c]);
#pragma unroll
        for (int mf = 0; mf < 4; mf++) {
            int r0 = e0 + m0 + mf * 16 + gid;
            float2 o0, o1;
            o0.x = 2.f * fmaxf(fmaf(a2.x, acc[mf][nf][0], b2.x), 0.f);
            o0.y = 2.f * fmaxf(fmaf(a2.y, acc[mf][nf][1], b2.y), 0.f);
            o1.x = 2.f * fmaxf(fmaf(a2.x, acc[mf][nf][2], b2.x), 0.f);
            o1.y = 2.f * fmaxf(fmaf(a2.y, acc[mf][nf][3], b2.y), 0.f);
            *reinterpret_cast<float2*>(&dst[(size_t)r0 * HH + c]) = o0;
            *reinterpret_cast<float2*>(&dst[(size_t)(r0 + 8) * HH + c]) = o1;
        }
    }
}

// ---------------- edge init (tf32 legacy mma path, K=64 padded) ----------------
#define AEP 68
#define BPEI 136
#define SMEM_EI ((128 * AEP + 2 * 64 * BPEI) * 4)

__global__ __launch_bounds__(256, 1) void k_edge_init(const float* __restrict__ x,
                                                      const float* __restrict__ eat,
                                                      const int* __restrict__ row,
                                                      const float* __restrict__ bei) {
    extern __shared__ float smei[];
    float* As = smei;                // [128][AEP]
    float* BsH = smei + 128 * AEP;   // [64][BPEI]
    float* BsL = BsH + 64 * BPEI;

    int tid = threadIdx.x;
    int e0 = blockIdx.x * 128;

    for (int i = tid; i < 2048; i += 256) {
        int k = i >> 5, n4 = (i & 31) << 2;
        *reinterpret_cast<float4*>(&BsH[k * BPEI + n4]) = reinterpret_cast<const float4*>(g_EiHi)[i];
        *reinterpret_cast<float4*>(&BsL[k * BPEI + n4]) = reinterpret_cast<const float4*>(g_EiLo)[i];
    }
    for (int i = tid; i < 2048; i += 256) {
        int m = i >> 4, k4 = i & 15;
        int e = e0 + m;
        float4 v;
        if (k4 < 12) {
            int r = __ldg(&row[e]);
            v = *reinterpret_cast<const float4*>(&x[(size_t)r * 48 + (k4 << 2)]);
        } else {
            int kb = k4 << 2;
            float t[4];
#pragma unroll
            for (int j = 0; j < 4; j++) {
                int kk = kb + j;
                t[j] = (kk < 61) ? eat[(size_t)e * 13 + (kk - 48)] : 0.f;
            }
            v = make_float4(t[0], t[1], t[2], t[3]);
        }
        *reinterpret_cast<float4*>(&As[m * AEP + (k4 << 2)]) = v;
    }
    __syncthreads();

    int lane = tid & 31, w = tid >> 5;
    int m0 = (w >> 2) * 64, n0 = (w & 3) * 32;
    int gid = lane >> 2, tg = lane & 3;

    float acc[4][4][4];
#pragma unroll
    for (int mf = 0; mf < 4; mf++)
#pragma unroll
        for (int nf = 0; nf < 4; nf++)
#pragma unroll
            for (int q = 0; q < 4; q++) acc[mf][nf][q] = 0.f;

#pragma unroll 1
    for (int ks = 0; ks < 8; ks++) {
        int k0 = ks * 8;
        unsigned ah[4][4], al[4][4];
#pragma unroll
        for (int mf = 0; mf < 4; mf++) {
            int mr = m0 + mf * 16 + gid;
            float a0 = As[mr * AEP + k0 + tg];
            float a1 = As[(mr + 8) * AEP + k0 + tg];
            float a2 = As[mr * AEP + k0 + tg + 4];
            float a3 = As[(mr + 8) * AEP + k0 + tg + 4];
            float h, l;
            tf32_split(a0, h, l); ah[mf][0] = __float_as_uint(h); al[mf][0] = __float_as_uint(l);
            tf32_split(a1, h, l); ah[mf][1] = __float_as_uint(h); al[mf][1] = __float_as_uint(l);
            tf32_split(a2, h, l); ah[mf][2] = __float_as_uint(h); al[mf][2] = __float_as_uint(l);
            tf32_split(a3, h, l); ah[mf][3] = __float_as_uint(h); al[mf][3] = __float_as_uint(l);
        }
        unsigned bh[4][2], bl[4][2];
#pragma unroll
        for (int nf = 0; nf < 4; nf++) {
            int nc = n0 + nf * 8 + gid;
            bh[nf][0] = __float_as_uint(BsH[(k0 + tg) * BPEI + nc]);
            bh[nf][1] = __float_as_uint(BsH[(k0 + tg + 4) * BPEI + nc]);
            bl[nf][0] = __float_as_uint(BsL[(k0 + tg) * BPEI + nc]);
            bl[nf][1] = __float_as_uint(BsL[(k0 + tg + 4) * BPEI + nc]);
        }
#pragma unroll
        for (int mf = 0; mf < 4; mf++)
#pragma unroll
            for (int nf = 0; nf < 4; nf++) {
                MMA_TF32(acc[mf][nf], ah[mf], bh[nf]);
                MMA_TF32(acc[mf][nf], al[mf], bh[nf]);
                MMA_TF32(acc[mf][nf], ah[mf], bl[nf]);
            }
    }

#pragma unroll
    for (int nf = 0; nf < 4; nf++) {
        int c = n0 + nf * 8 + 2 * tg;
        float2 b2 = *reinterpret_cast<const float2*>(&bei[c]);
#pragma unroll
        for (int mf = 0; mf < 4; mf++) {
            int r0 = e0 + m0 + mf * 16 + gid;
            float2 o0, o1;
            o0.x = fmaxf(acc[mf][nf][0] + b2.x, 0.f);
            o0.y = fmaxf(acc[mf][nf][1] + b2.y, 0.f);
            o1.x = fmaxf(acc[mf][nf][2] + b2.x, 0.f);
            o1.y = fmaxf(acc[mf][nf][3] + b2.y, 0.f);
            *reinterpret_cast<float2*>(&g_bufA[(size_t)r0 * HH + c]) = o0;
            *reinterpret_cast<float2*>(&g_bufA[(size_t)(r0 + 8) * HH + c]) = o1;
        }
    }
}

// ---------------- pooling + FFN + sigmoid ----------------
__global__ __launch_bounds__(256) void k_pool(const int* __restrict__ batch,
                                              const float* __restrict__ fW,
                                              const float* __restrict__ fb,
                                              float* __restrict__ out) {
    int g = (blockIdx.x * 256 + threadIdx.x) >> 5;
    int lane = threadIdx.x & 31;
    if (g >= GG) return;
    int s, e;
    {
        int lo = 0, hi = NN;
        while (lo < hi) { int mid = (lo + hi) >> 1; if (batch[mid] < g) lo = mid + 1; else hi = mid; }
        s = lo;
    }
    {
        int lo = s, hi = NN;
        while (lo < hi) { int mid = (lo + hi) >> 1; if (batch[mid] < g + 1) lo = mid + 1; else hi = mid; }
        e = lo;
    }
    float4 acc = make_float4(0.f, 0.f, 0.f, 0.f);
    for (int n = s; n < e; n++) {
        float4 v = reinterpret_cast<const float4*>(g_amsg)[(size_t)n * 32 + lane];
        acc.x += v.x; acc.y += v.y; acc.z += v.z; acc.w += v.w;
    }
    float4 w = reinterpret_cast<const float4*>(fW)[lane];
    float dot = acc.x * w.x + acc.y * w.y + acc.z * w.z + acc.w * w.w;
#pragma unroll
    for (int off = 16; off; off >>= 1) dot += __shfl_down_sync(0xffffffffu, dot, off);
    if (lane == 0) {
        int cnt = e - s;
        float c = (float)(cnt > 0 ? cnt : 1);
        float z = dot / c + fb[0];
        out[g] = 1.f / (1.f + expf(-z));
    }
}

// ---------------- launch ----------------
extern "C" void kernel_launch(void* const* d_in, const int* in_sizes, int n_in,
                              void* d_out, int out_size) {
    const float* x     = (const float*)d_in[0];
    const float* eat   = (const float*)d_in[1];
    const int*   eidx  = (const int*)d_in[2];
    const int*   batch = (const int*)d_in[3];
    const float* Wei   = (const float*)d_in[6];
    const float* bei   = (const float*)d_in[7];
    const float* convW = (const float*)d_in[8];
    const float* convb = (const float*)d_in[9];
    const float* gam   = (const float*)d_in[10];
    const float* bet   = (const float*)d_in[11];
    const float* rm    = (const float*)d_in[12];
    const float* rv    = (const float*)d_in[13];
    const float* fW    = (const float*)d_in[14];
    const float* fb    = (const float*)d_in[15];
    float* out = (float*)d_out;

    const int* row = eidx;
    const int* col = eidx + EE;

    cudaFuncSetAttribute(k_gemm, cudaFuncAttributeMaxDynamicSharedMemorySize, SMEM_GEMM);
    cudaFuncSetAttribute(k_edge_init, cudaFuncAttributeMaxDynamicSharedMemorySize, SMEM_EI);

    // CSR build (deterministic after sort)
    k_zero_cnt<<<(NN + 255) / 256, 256>>>();
    k_count<<<(EE + 255) / 256, 256>>>(col);
    k_scan<<<1, 1024>>>();
    k_scatter<<<(EE + 255) / 256, 256>>>(col);
    k_sortcsr<<<(NN + 255) / 256, 256>>>();

    // parameter prep
    k_prep_w<<<(DD * HH * HH + 255) / 256, 256>>>(convW);
    k_prep_wei<<<(64 * HH + 255) / 256, 256>>>(Wei);
    k_prep_bn<<<(DD * HH + 255) / 256, 256>>>(convb, gam, bet, rm, rv);

    // edge init -> bufA
    k_edge_init<<<EE / 128, 256, SMEM_EI>>>(x, eat, row, bei);

    // 15 DMPNN layers, ping-pong A<->B
    for (int d = 0; d < DD; d++) {
        int flip = d & 1;
        k_amsg<<<(NN * 32 + 255) / 256, 256>>>(flip);
        k_gemm<<<EE / 128, 256, SMEM_GEMM>>>(flip, d, row);
    }

    // final node aggregation from bufB, then pool+FFN
    k_amsg<<<(NN * 32 + 255) / 256, 256>>>(1);
    k_pool<<<(GG * 32 + 255) / 256, 256>>>(batch, fW, fb, out);
}

// round 8
// speedup vs baseline: 1.3643x; 1.3643x over previous
#include <cuda_runtime.h>
#include <cuda_bf16.h>
#include <cstdint>

#define NN 50000
#define EE 400000
#define HH 128
#define DD 15
#define GG 256

// ---------------- device scratch (no allocations allowed) ----------------
__device__ __align__(16) float g_bufA[(size_t)EE * HH];
__device__ __align__(16) float g_bufB[(size_t)EE * HH];
__device__ __align__(16) float g_amsg[(size_t)NN * HH];
// conv weights packed: [d][n][pair] -> uint2{ (h(2p),h(2p+1)) , (l(2p),l(2p+1)) }
__device__ __align__(16) uint2 g_Wpk[DD * HH * 64];
// edge-init weights (tf32 2-limb legacy path)
__device__ __align__(16) float g_EiHi[64 * HH];
__device__ __align__(16) float g_EiLo[64 * HH];
__device__ __align__(16) float g_alpha[DD * HH];
__device__ __align__(16) float g_beta[DD * HH];
__device__ int g_cnt[NN];
__device__ int g_rowptr[NN + 1];
__device__ int g_cursor[NN];
__device__ int g_csr[EE];

// ---------------- helpers ----------------
__device__ __forceinline__ void tf32_split(float v, float& hi, float& lo) {
    unsigned h;
    asm("cvt.rna.tf32.f32 %0, %1;" : "=r"(h) : "f"(v));
    float hf = __uint_as_float(h);
    float r = v - hf;
    unsigned l;
    asm("cvt.rna.tf32.f32 %0, %1;" : "=r"(l) : "f"(r));
    hi = hf;
    lo = __uint_as_float(l);
}

__device__ __forceinline__ void bf16_split2(float v, __nv_bfloat16& h, __nv_bfloat16& l) {
    h = __float2bfloat16(v);
    l = __float2bfloat16(v - __bfloat162float(h));
}

__device__ __forceinline__ unsigned pack2(__nv_bfloat16 a, __nv_bfloat16 b) {
    __nv_bfloat162 t = __halves2bfloat162(a, b);
    return *reinterpret_cast<unsigned*>(&t);
}

#define MMA_TF32(c, a, b)                                                    \
    asm volatile(                                                            \
        "mma.sync.aligned.m16n8k8.row.col.f32.tf32.tf32.f32 "                \
        "{%0,%1,%2,%3},{%4,%5,%6,%7},{%8,%9},{%0,%1,%2,%3};"                 \
        : "+f"((c)[0]), "+f"((c)[1]), "+f"((c)[2]), "+f"((c)[3])             \
        : "r"((a)[0]), "r"((a)[1]), "r"((a)[2]), "r"((a)[3]),                \
          "r"((b)[0]), "r"((b)[1]))

#define MMA_BF16(c, a, b)                                                    \
    asm volatile(                                                            \
        "mma.sync.aligned.m16n8k16.row.col.f32.bf16.bf16.f32 "               \
        "{%0,%1,%2,%3},{%4,%5,%6,%7},{%8,%9},{%0,%1,%2,%3};"                 \
        : "+f"((c)[0]), "+f"((c)[1]), "+f"((c)[2]), "+f"((c)[3])             \
        : "r"((a)[0]), "r"((a)[1]), "r"((a)[2]), "r"((a)[3]),                \
          "r"((b)[0]), "r"((b)[1]))

#define LDS64(r0, r1, addr)                                                  \
    asm volatile("ld.shared.v2.u32 {%0,%1}, [%2];" : "=r"(r0), "=r"(r1) : "r"(addr))

// ---------------- CSR build (by col) ----------------
__global__ void k_zero_cnt() {
    int i = blockIdx.x * blockDim.x + threadIdx.x;
    if (i < NN) g_cnt[i] = 0;
}

__global__ void k_count(const int* __restrict__ col) {
    int e = blockIdx.x * blockDim.x + threadIdx.x;
    if (e < EE) atomicAdd(&g_cnt[col[e]], 1);
}

__global__ void k_scan() {
    __shared__ int sh[1024];
    int t = threadIdx.x;
    const int C = (NN + 1023) / 1024;
    int base = t * C;
    int s = 0;
    for (int j = 0; j < C; j++) {
        int i = base + j;
        if (i < NN) s += g_cnt[i];
    }
    sh[t] = s;
    __syncthreads();
    for (int off = 1; off < 1024; off <<= 1) {
        int v = (t >= off) ? sh[t - off] : 0;
        __syncthreads();
        sh[t] += v;
        __syncthreads();
    }
    int run = sh[t] - s;
    for (int j = 0; j < C; j++) {
        int i = base + j;
        if (i < NN) {
            g_rowptr[i] = run;
            g_cursor[i] = run;
            run += g_cnt[i];
        }
    }
    if (t == 0) g_rowptr[NN] = EE;
}

__global__ void k_scatter(const int* __restrict__ col) {
    int e = blockIdx.x * blockDim.x + threadIdx.x;
    if (e < EE) {
        int pos = atomicAdd(&g_cursor[col[e]], 1);
        g_csr[pos] = e;
    }
}

__global__ void k_sortcsr() {
    int i = blockIdx.x * blockDim.x + threadIdx.x;
    if (i >= NN) return;
    int s = g_rowptr[i], e = g_rowptr[i + 1];
    for (int a = s + 1; a < e; a++) {
        int v = g_csr[a];
        int b = a - 1;
        while (b >= s && g_csr[b] > v) { g_csr[b + 1] = g_csr[b]; b--; }
        g_csr[b + 1] = v;
    }
}

// ---------------- parameter prep ----------------
// pack W[d][n][k] into per-k-pair interleaved hi/lo limbs
__global__ void k_prep_w(const float* __restrict__ W) {
    int idx = blockIdx.x * blockDim.x + threadIdx.x;
    if (idx >= DD * HH * 64) return;
    int p = idx & 63;
    int dn = idx >> 6;  // d*128+n
    const float* src = W + (size_t)dn * HH + 2 * p;
    __nv_bfloat16 h0, h1, l0, l1;
    bf16_split2(src[0], h0, l0);
    bf16_split2(src[1], h1, l1);
    g_Wpk[idx] = make_uint2(pack2(h0, h1), pack2(l0, l1));
}

__global__ void k_prep_wei(const float* __restrict__ W) {
    int idx = blockIdx.x * blockDim.x + threadIdx.x;
    if (idx >= 64 * HH) return;
    int k = idx >> 7, o = idx & 127;
    float v = (k < 61) ? W[o * 61 + k] : 0.f;
    float hi, lo;
    tf32_split(v, hi, lo);
    g_EiHi[idx] = hi;
    g_EiLo[idx] = lo;
}

__global__ void k_prep_bn(const float* __restrict__ b, const float* __restrict__ gm,
                          const float* __restrict__ bt, const float* __restrict__ rm,
                          const float* __restrict__ rv) {
    int idx = blockIdx.x * blockDim.x + threadIdx.x;
    if (idx >= DD * HH) return;
    float al = gm[idx] * rsqrtf(rv[idx] + 1e-5f);
    g_alpha[idx] = al;
    g_beta[idx] = al * (b[idx] - rm[idx]) + bt[idx];
}

// ---------------- a_msg / h_node: warp-per-node CSR gather ----------------
__global__ __launch_bounds__(256) void k_amsg(int flip) {
    const float* __restrict__ src = flip ? g_bufB : g_bufA;
    int w = (blockIdx.x * 256 + threadIdx.x) >> 5;
    int lane = threadIdx.x & 31;
    if (w >= NN) return;
    int s = g_rowptr[w], e = g_rowptr[w + 1];
    float4 acc = make_float4(0.f, 0.f, 0.f, 0.f);
    for (int j = s; j < e; j++) {
        int ed = g_csr[j];
        float4 v = reinterpret_cast<const float4*>(src)[(size_t)ed * 32 + lane];
        acc.x += v.x; acc.y += v.y; acc.z += v.z; acc.w += v.w;
    }
    reinterpret_cast<float4*>(g_amsg)[(size_t)w * 32 + lane] = acc;
}

// ---------------- fused DMPNN layer GEMM ----------------
// M-tile 64 edges, N 128, interleaved hi/lo limbs, 2 CTAs/SM
// dst[e] = 2*relu(alpha * ((a_msg[row[e]] - src[e^1]) @ W^T) + beta)
#define PAB 544  // bytes per row: 64 pairs * 8B + 32B pad -> 8-bank row shift
#define A_OFF 1024
#define B_OFF (A_OFF + 64 * PAB)
#define SMEM_GEMM (B_OFF + 128 * PAB)

__global__ __launch_bounds__(256, 2) void k_gemm(int flip, int layer,
                                                 const int* __restrict__ row) {
    const float* __restrict__ src = flip ? g_bufB : g_bufA;
    float* __restrict__ dst = flip ? g_bufA : g_bufB;
    extern __shared__ __align__(16) char smg[];
    float* als = (float*)smg;
    float* bes = als + 128;
    char* Asm = smg + A_OFF;
    char* Bsm = smg + B_OFF;

    int tid = threadIdx.x;
    int e0 = blockIdx.x * 64;

    if (tid < 128) {
        als[tid] = g_alpha[layer * HH + tid];
        bes[tid] = g_beta[layer * HH + tid];
    }

    // B: copy packed weights (128 rows x 32 uint4)
    {
        const uint4* wp = (const uint4*)(g_Wpk + (size_t)layer * HH * 64);
        for (int i = tid; i < 4096; i += 256) {
            int n = i >> 5, c = i & 31;
            *reinterpret_cast<uint4*>(Bsm + n * PAB + c * 16) = wp[i];
        }
    }

    // A: msg = a_msg[row[e]] - src[e^1]; pack [h01,l01,h23,l23] per float4
    for (int i = tid; i < 2048; i += 256) {
        int m = i >> 5, k4 = i & 31;
        int e = e0 + m;
        int r = __ldg(&row[e]);
        float4 am = reinterpret_cast<const float4*>(g_amsg)[(size_t)r * 32 + k4];
        float4 rv = reinterpret_cast<const float4*>(src)[((size_t)(e ^ 1)) * 32 + k4];
        float v0 = am.x - rv.x, v1 = am.y - rv.y, v2 = am.z - rv.z, v3 = am.w - rv.w;
        __nv_bfloat16 h0, h1, h2, h3, l0, l1, l2, l3;
        bf16_split2(v0, h0, l0);
        bf16_split2(v1, h1, l1);
        bf16_split2(v2, h2, l2);
        bf16_split2(v3, h3, l3);
        uint4 val = make_uint4(pack2(h0, h1), pack2(l0, l1), pack2(h2, h3), pack2(l2, l3));
        *reinterpret_cast<uint4*>(Asm + m * PAB + k4 * 16) = val;
    }
    __syncthreads();

    int lane = tid & 31, w = tid >> 5;
    int m0 = (w >> 2) * 32, n0 = (w & 3) * 32;
    int gid = lane >> 2, tg = lane & 3;

    unsigned aBase = (unsigned)__cvta_generic_to_shared(Asm + (m0 + gid) * PAB + tg * 8);
    unsigned bBase = (unsigned)__cvta_generic_to_shared(Bsm + (n0 + gid) * PAB + tg * 8);

    float acc[2][4][4];
#pragma unroll
    for (int mf = 0; mf < 2; mf++)
#pragma unroll
        for (int nf = 0; nf < 4; nf++)
#pragma unroll
            for (int q = 0; q < 4; q++) acc[mf][nf][q] = 0.f;

#pragma unroll 2
    for (int ks = 0; ks < 8; ks++) {
        unsigned koff = ks * 64;  // 8 pairs * 8B
        unsigned ah[2][4], al[2][4];
#pragma unroll
        for (int mf = 0; mf < 2; mf++) {
            unsigned o = aBase + mf * (16 * PAB) + koff;
            LDS64(ah[mf][0], al[mf][0], o);
            LDS64(ah[mf][2], al[mf][2], o + 32);
            LDS64(ah[mf][1], al[mf][1], o + 8 * PAB);
            LDS64(ah[mf][3], al[mf][3], o + 8 * PAB + 32);
        }
        unsigned bh[4][2], bl[4][2];
#pragma unroll
        for (int nf = 0; nf < 4; nf++) {
            unsigned o = bBase + nf * (8 * PAB) + koff;
            LDS64(bh[nf][0], bl[nf][0], o);
            LDS64(bh[nf][1], bl[nf][1], o + 32);
        }
#pragma unroll
        for (int mf = 0; mf < 2; mf++)
#pragma unroll
            for (int nf = 0; nf < 4; nf++) {
                MMA_BF16(acc[mf][nf], ah[mf], bh[nf]);
                MMA_BF16(acc[mf][nf], ah[mf], bl[nf]);
                MMA_BF16(acc[mf][nf], al[mf], bh[nf]);
            }
    }

    // epilogue: 2*relu(alpha*acc + beta)
#pragma unroll
    for (int nf = 0; nf < 4; nf++) {
        int c = n0 + nf * 8 + 2 * tg;
        float2 a2 = *reinterpret_cast<const float2*>(&als[c]);
        float2 b2 = *reinterpret_cast<const float2*>(&bes[c]);
#pragma unroll
        for (int mf = 0; mf < 2; mf++) {
            int r0 = e0 + m0 + mf * 16 + gid;
            float2 o0, o1;
            o0.x = 2.f * fmaxf(fmaf(a2.x, acc[mf][nf][0], b2.x), 0.f);
            o0.y = 2.f * fmaxf(fmaf(a2.y, acc[mf][nf][1], b2.y), 0.f);
            o1.x = 2.f * fmaxf(fmaf(a2.x, acc[mf][nf][2], b2.x), 0.f);
            o1.y = 2.f * fmaxf(fmaf(a2.y, acc[mf][nf][3], b2.y), 0.f);
            *reinterpret_cast<float2*>(&dst[(size_t)r0 * HH + c]) = o0;
            *reinterpret_cast<float2*>(&dst[(size_t)(r0 + 8) * HH + c]) = o1;
        }
    }
}

// ---------------- edge init (tf32 legacy mma path, K=64 padded) ----------------
#define AEP 68
#define BPEI 136
#define SMEM_EI ((128 * AEP + 2 * 64 * BPEI) * 4)

__global__ __launch_bounds__(256, 1) void k_edge_init(const float* __restrict__ x,
                                                      const float* __restrict__ eat,
                                                      const int* __restrict__ row,
                                                      const float* __restrict__ bei) {
    extern __shared__ float smei[];
    float* As = smei;                // [128][AEP]
    float* BsH = smei + 128 * AEP;   // [64][BPEI]
    float* BsL = BsH + 64 * BPEI;

    int tid = threadIdx.x;
    int e0 = blockIdx.x * 128;

    for (int i = tid; i < 2048; i += 256) {
        int k = i >> 5, n4 = (i & 31) << 2;
        *reinterpret_cast<float4*>(&BsH[k * BPEI + n4]) = reinterpret_cast<const float4*>(g_EiHi)[i];
        *reinterpret_cast<float4*>(&BsL[k * BPEI + n4]) = reinterpret_cast<const float4*>(g_EiLo)[i];
    }
    for (int i = tid; i < 2048; i += 256) {
        int m = i >> 4, k4 = i & 15;
        int e = e0 + m;
        float4 v;
        if (k4 < 12) {
            int r = __ldg(&row[e]);
            v = *reinterpret_cast<const float4*>(&x[(size_t)r * 48 + (k4 << 2)]);
        } else {
            int kb = k4 << 2;
            float t[4];
#pragma unroll
            for (int j = 0; j < 4; j++) {
                int kk = kb + j;
                t[j] = (kk < 61) ? eat[(size_t)e * 13 + (kk - 48)] : 0.f;
            }
            v = make_float4(t[0], t[1], t[2], t[3]);
        }
        *reinterpret_cast<float4*>(&As[m * AEP + (k4 << 2)]) = v;
    }
    __syncthreads();

    int lane = tid & 31, w = tid >> 5;
    int m0 = (w >> 2) * 64, n0 = (w & 3) * 32;
    int gid = lane >> 2, tg = lane & 3;

    float acc[4][4][4];
#pragma unroll
    for (int mf = 0; mf < 4; mf++)
#pragma unroll
        for (int nf = 0; nf < 4; nf++)
#pragma unroll
            for (int q = 0; q < 4; q++) acc[mf][nf][q] = 0.f;

#pragma unroll 1
    for (int ks = 0; ks < 8; ks++) {
        int k0 = ks * 8;
        unsigned ah[4][4], al[4][4];
#pragma unroll
        for (int mf = 0; mf < 4; mf++) {
            int mr = m0 + mf * 16 + gid;
            float a0 = As[mr * AEP + k0 + tg];
            float a1 = As[(mr + 8) * AEP + k0 + tg];
            float a2 = As[mr * AEP + k0 + tg + 4];
            float a3 = As[(mr + 8) * AEP + k0 + tg + 4];
            float h, l;
            tf32_split(a0, h, l); ah[mf][0] = __float_as_uint(h); al[mf][0] = __float_as_uint(l);
            tf32_split(a1, h, l); ah[mf][1] = __float_as_uint(h); al[mf][1] = __float_as_uint(l);
            tf32_split(a2, h, l); ah[mf][2] = __float_as_uint(h); al[mf][2] = __float_as_uint(l);
            tf32_split(a3, h, l); ah[mf][3] = __float_as_uint(h); al[mf][3] = __float_as_uint(l);
        }
        unsigned bh[4][2], bl[4][2];
#pragma unroll
        for (int nf = 0; nf < 4; nf++) {
            int nc = n0 + nf * 8 + gid;
            bh[nf][0] = __float_as_uint(BsH[(k0 + tg) * BPEI + nc]);
            bh[nf][1] = __float_as_uint(BsH[(k0 + tg + 4) * BPEI + nc]);
            bl[nf][0] = __float_as_uint(BsL[(k0 + tg) * BPEI + nc]);
            bl[nf][1] = __float_as_uint(BsL[(k0 + tg + 4) * BPEI + nc]);
        }
#pragma unroll
        for (int mf = 0; mf < 4; mf++)
#pragma unroll
            for (int nf = 0; nf < 4; nf++) {
                MMA_TF32(acc[mf][nf], ah[mf], bh[nf]);
                MMA_TF32(acc[mf][nf], al[mf], bh[nf]);
                MMA_TF32(acc[mf][nf], ah[mf], bl[nf]);
            }
    }

#pragma unroll
    for (int nf = 0; nf < 4; nf++) {
        int c = n0 + nf * 8 + 2 * tg;
        float2 b2 = *reinterpret_cast<const float2*>(&bei[c]);
#pragma unroll
        for (int mf = 0; mf < 4; mf++) {
            int r0 = e0 + m0 + mf * 16 + gid;
            float2 o0, o1;
            o0.x = fmaxf(acc[mf][nf][0] + b2.x, 0.f);
            o0.y = fmaxf(acc[mf][nf][1] + b2.y, 0.f);
            o1.x = fmaxf(acc[mf][nf][2] + b2.x, 0.f);
            o1.y = fmaxf(acc[mf][nf][3] + b2.y, 0.f);
            *reinterpret_cast<float2*>(&g_bufA[(size_t)r0 * HH + c]) = o0;
            *reinterpret_cast<float2*>(&g_bufA[(size_t)(r0 + 8) * HH + c]) = o1;
        }
    }
}

// ---------------- pooling + FFN + sigmoid ----------------
__global__ __launch_bounds__(256) void k_pool(const int* __restrict__ batch,
                                              const float* __restrict__ fW,
                                              const float* __restrict__ fb,
                                              float* __restrict__ out) {
    int g = (blockIdx.x * 256 + threadIdx.x) >> 5;
    int lane = threadIdx.x & 31;
    if (g >= GG) return;
    int s, e;
    {
        int lo = 0, hi = NN;
        while (lo < hi) { int mid = (lo + hi) >> 1; if (batch[mid] < g) lo = mid + 1; else hi = mid; }
        s = lo;
    }
    {
        int lo = s, hi = NN;
        while (lo < hi) { int mid = (lo + hi) >> 1; if (batch[mid] < g + 1) lo = mid + 1; else hi = mid; }
        e = lo;
    }
    float4 acc = make_float4(0.f, 0.f, 0.f, 0.f);
    for (int n = s; n < e; n++) {
        float4 v = reinterpret_cast<const float4*>(g_amsg)[(size_t)n * 32 + lane];
        acc.x += v.x; acc.y += v.y; acc.z += v.z; acc.w += v.w;
    }
    float4 w = reinterpret_cast<const float4*>(fW)[lane];
    float dot = acc.x * w.x + acc.y * w.y + acc.z * w.z + acc.w * w.w;
#pragma unroll
    for (int off = 16; off; off >>= 1) dot += __shfl_down_sync(0xffffffffu, dot, off);
    if (lane == 0) {
        int cnt = e - s;
        float c = (float)(cnt > 0 ? cnt : 1);
        float z = dot / c + fb[0];
        out[g] = 1.f / (1.f + expf(-z));
    }
}

// ---------------- launch ----------------
extern "C" void kernel_launch(void* const* d_in, const int* in_sizes, int n_in,
                              void* d_out, int out_size) {
    const float* x     = (const float*)d_in[0];
    const float* eat   = (const float*)d_in[1];
    const int*   eidx  = (const int*)d_in[2];
    const int*   batch = (const int*)d_in[3];
    const float* Wei   = (const float*)d_in[6];
    const float* bei   = (const float*)d_in[7];
    const float* convW = (const float*)d_in[8];
    const float* convb = (const float*)d_in[9];
    const float* gam   = (const float*)d_in[10];
    const float* bet   = (const float*)d_in[11];
    const float* rm    = (const float*)d_in[12];
    const float* rv    = (const float*)d_in[13];
    const float* fW    = (const float*)d_in[14];
    const float* fb    = (const float*)d_in[15];
    float* out = (float*)d_out;

    const int* row = eidx;
    const int* col = eidx + EE;

    cudaFuncSetAttribute(k_gemm, cudaFuncAttributeMaxDynamicSharedMemorySize, SMEM_GEMM);
    cudaFuncSetAttribute(k_edge_init, cudaFuncAttributeMaxDynamicSharedMemorySize, SMEM_EI);

    // CSR build (deterministic after sort)
    k_zero_cnt<<<(NN + 255) / 256, 256>>>();
    k_count<<<(EE + 255) / 256, 256>>>(col);
    k_scan<<<1, 1024>>>();
    k_scatter<<<(EE + 255) / 256, 256>>>(col);
    k_sortcsr<<<(NN + 255) / 256, 256>>>();

    // parameter prep
    k_prep_w<<<(DD * HH * 64 + 255) / 256, 256>>>(convW);
    k_prep_wei<<<(64 * HH + 255) / 256, 256>>>(Wei);
    k_prep_bn<<<(DD * HH + 255) / 256, 256>>>(convb, gam, bet, rm, rv);

    // edge init -> bufA
    k_edge_init<<<EE / 128, 256, SMEM_EI>>>(x, eat, row, bei);

    // 15 DMPNN layers, ping-pong A<->B
    for (int d = 0; d < DD; d++) {
        int flip = d & 1;
        k_amsg<<<(NN * 32 + 255) / 256, 256>>>(flip);
        k_gemm<<<EE / 64, 256, SMEM_GEMM>>>(flip, d, row);
    }

    // final node aggregation from bufB, then pool+FFN
    k_amsg<<<(NN * 32 + 255) / 256, 256>>>(1);
    k_pool<<<(GG * 32 + 255) / 256, 256>>>(batch, fW, fb, out);
}